// round 15
// baseline (speedup 1.0000x reference)
#include <cuda_runtime.h>
#include <cuda_fp16.h>
#include <cstdint>

#define Bsz 2
#define Ssz 2048
#define Dsz 2048
#define Hn 16
#define DHsz 128
#define Msz (Bsz*Ssz)

__device__ __align__(16) __half g_xh[(size_t)Msz*Dsz];
__device__ __align__(16) __half g_Wh[4][(size_t)Dsz*Dsz];
__device__ __align__(16) __half g_Qh[(size_t)Msz*Dsz];
__device__ __align__(16) __half g_Kh[(size_t)Msz*Dsz];
__device__ __align__(16) __half g_Vh[(size_t)Msz*Dsz];
__device__ __align__(16) __half g_Ah[(size_t)Msz*Dsz];   // 1024 * w * V

#define ASCALE 1024.0f
#define AINV   0.0009765625f

__device__ __forceinline__ uint32_t smem_u32(const void* p) {
    uint32_t a;
    asm("{ .reg .u64 t; cvta.to.shared.u64 t, %1; cvt.u32.u64 %0, t; }" : "=r"(a) : "l"(p));
    return a;
}
__device__ __forceinline__ void ldsm4(uint32_t* r, uint32_t a) {
    asm volatile("ldmatrix.sync.aligned.m8n8.x4.shared.b16 {%0,%1,%2,%3}, [%4];"
                 : "=r"(r[0]), "=r"(r[1]), "=r"(r[2]), "=r"(r[3]) : "r"(a));
}
__device__ __forceinline__ void mma16816(float* c, const uint32_t* a, uint32_t b0, uint32_t b1) {
    asm volatile("mma.sync.aligned.m16n8k16.row.col.f32.f16.f16.f32 "
                 "{%0,%1,%2,%3},{%4,%5,%6,%7},{%8,%9},{%0,%1,%2,%3};"
                 : "+f"(c[0]), "+f"(c[1]), "+f"(c[2]), "+f"(c[3])
                 : "r"(a[0]), "r"(a[1]), "r"(a[2]), "r"(a[3]), "r"(b0), "r"(b1));
}
#define CP16(dst, src) asm volatile("cp.async.cg.shared.global [%0], [%1], 16;" :: "r"(dst), "l"(src))
#define CP_COMMIT()    asm volatile("cp.async.commit_group;" ::: "memory")
#define CP_WAIT1()     asm volatile("cp.async.wait_group 1;" ::: "memory")
#define CP_WAIT0()     asm volatile("cp.async.wait_group 0;" ::: "memory")

// ---------------- single fused fp32 -> fp16 conversion (x + all 4 W) ----------------
#define XCHUNKS 1048576   // Msz*Dsz/8
#define WCHUNKS 524288    // Dsz*Dsz/8

__global__ __launch_bounds__(256) void conv_all(const float* __restrict__ x,
                                                const float* __restrict__ w0,
                                                const float* __restrict__ w1,
                                                const float* __restrict__ w2,
                                                const float* __restrict__ w3) {
    int i = blockIdx.x * 256 + threadIdx.x;
    const float* src;
    __half* dst;
    size_t off;
    if (i < XCHUNKS) {
        src = x; dst = g_xh; off = (size_t)i * 8;
    } else {
        int r = i - XCHUNKS;
        int sel = r >> 19;
        off = (size_t)(r & (WCHUNKS - 1)) * 8;
        src = (sel == 0) ? w0 : (sel == 1) ? w1 : (sel == 2) ? w2 : w3;
        dst = g_Wh[sel];
    }
    float4 v0 = *(const float4*)(src + off);
    float4 v1 = *(const float4*)(src + off + 4);
    __half2 h[4];
    h[0] = __floats2half2_rn(v0.x, v0.y);
    h[1] = __floats2half2_rn(v0.z, v0.w);
    h[2] = __floats2half2_rn(v1.x, v1.y);
    h[3] = __floats2half2_rn(v1.z, v1.w);
    *(uint4*)(dst + off) = *(uint4*)h;
}

// ---------------- GEMM: 1-pass fp16, K=64 slabs, 3-stage cp.async ----------------
#define KBUF 16384u
#define G_SMEM 98304

__global__ __launch_bounds__(256, 2) void gemm_mma(const float* __restrict__ rc,
                                                   const float* __restrict__ rs,
                                                   float* __restrict__ Co, int mode) {
    extern __shared__ __align__(16) char smem[];
    const int tid = threadIdx.x, w = tid >> 5, lane = tid & 31;
    const int wm = w & 3, wn = w >> 2;
    const int m0 = blockIdx.x * 128;
    const int wsel = (mode == 3) ? 3 : (blockIdx.y >> 4);
    const int n0 = (mode == 3) ? blockIdx.y * 128 : (blockIdx.y & 15) * 128;
    const __half* Ah = (mode == 3) ? g_Ah : g_xh;
    const __half* Bh = g_Wh[wsel];

    float acc[64];
#pragma unroll
    for (int i = 0; i < 64; i++) acc[i] = 0.f;

    const uint32_t sA = smem_u32(smem), sB = sA + 3 * KBUF;
    uint32_t doff[4];
    const __half* pA[4];
    const __half* pB[4];
#pragma unroll
    for (int i = 0; i < 4; i++) {
        int u = tid + (i << 8);
        int r = u >> 3, ch = u & 7;
        doff[i] = (uint32_t)(r * 128 + ((ch ^ (r & 7)) << 4));
        pA[i] = Ah + (size_t)(m0 + r) * Dsz + ch * 8;
        pB[i] = Bh + (size_t)(n0 + r) * Dsz + ch * 8;
    }
    const uint32_t lanehi4 = (uint32_t)((lane >> 4) << 4);
    uint32_t baseA[2], baseB[4];
    {
        int rA0 = wm * 32 + (lane & 15);
#pragma unroll
        for (int mi = 0; mi < 2; mi++) {
            int r = rA0 + mi * 16;
            baseA[mi] = (uint32_t)(r * 128 + ((r & 7) << 4));
        }
#pragma unroll
        for (int nb = 0; nb < 4; nb++) {
            int r = wn * 64 + nb * 16 + (lane & 15);
            baseB[nb] = (uint32_t)(r * 128 + ((r & 7) << 4));
        }
    }
    const int NS = 32;

#define G_ISSUE(bi) do {                                                       \
        uint32_t _ba = sA + (uint32_t)(bi) * KBUF;                             \
        uint32_t _bb = sB + (uint32_t)(bi) * KBUF;                             \
        _Pragma("unroll")                                                      \
        for (int _i = 0; _i < 4; _i++) {                                       \
            CP16(_ba + doff[_i], pA[_i]);                                      \
            CP16(_bb + doff[_i], pB[_i]);                                      \
            pA[_i] += 64; pB[_i] += 64;                                        \
        }                                                                      \
        CP_COMMIT();                                                            \
    } while (0)

    G_ISSUE(0);
    G_ISSUE(1);

    int bi = 0, ii = 2;
    for (int s = 0; s < NS; s++) {
        if (s + 1 < NS) CP_WAIT1(); else CP_WAIT0();
        __syncthreads();
        if (s + 2 < NS) {
            G_ISSUE(ii);
            ii = (ii == 2) ? 0 : ii + 1;
        }
        uint32_t bufA = sA + (uint32_t)bi * KBUF;
        uint32_t bufB = sB + (uint32_t)bi * KBUF;
        bi = (bi == 2) ? 0 : bi + 1;

        uint32_t am[2][4], bm[2][4][4];
        // preload B fragments for ks=0
#pragma unroll
        for (int nb = 0; nb < 4; nb++)
            ldsm4(bm[0][nb], bufB + (baseB[nb] ^ lanehi4));
#pragma unroll
        for (int ks = 0; ks < 4; ks++) {
            uint32_t cbx = (uint32_t)(ks << 5) | lanehi4;
#pragma unroll
            for (int mi = 0; mi < 2; mi++)
                ldsm4(am[mi], bufA + (baseA[mi] ^ cbx));
            if (ks < 3) {
                uint32_t cbn = (uint32_t)((ks + 1) << 5) | lanehi4;
#pragma unroll
                for (int nb = 0; nb < 4; nb++)
                    ldsm4(bm[(ks + 1) & 1][nb], bufB + (baseB[nb] ^ cbn));
            }
            const int c = ks & 1;
#pragma unroll
            for (int mi = 0; mi < 2; mi++)
#pragma unroll
                for (int nb = 0; nb < 4; nb++) {
                    mma16816(&acc[(mi * 8 + nb * 2 + 0) * 4], am[mi], bm[c][nb][0], bm[c][nb][2]);
                    mma16816(&acc[(mi * 8 + nb * 2 + 1) * 4], am[mi], bm[c][nb][1], bm[c][nb][3]);
                }
        }
    }

    // epilogue
    const int l4 = lane >> 2, lm = lane & 3;
    __half* dsth = (wsel == 0) ? g_Qh : (wsel == 1) ? g_Kh : g_Vh;
#pragma unroll
    for (int mi = 0; mi < 2; mi++)
#pragma unroll
        for (int nb = 0; nb < 4; nb++)
#pragma unroll
            for (int j = 0; j < 2; j++)
#pragma unroll
                for (int rh = 0; rh < 2; rh++) {
                    float v0 = acc[(mi * 8 + nb * 2 + j) * 4 + rh * 2 + 0];
                    float v1 = acc[(mi * 8 + nb * 2 + j) * 4 + rh * 2 + 1];
                    int row = m0 + wm * 32 + mi * 16 + l4 + rh * 8;
                    int col = n0 + wn * 64 + nb * 16 + j * 8 + lm * 2;
                    size_t idx = ((size_t)row << 11) + col;
                    if (mode == 3) {
                        *(float2*)(Co + idx) = make_float2(v0 * AINV, v1 * AINV);
                    } else if (wsel <= 1) {
                        int p = (col & 127) >> 1, srow = row & (Ssz - 1);
                        float cc = rc[srow * 64 + p], sn = rs[srow * 64 + p];
                        float re = v0 * cc - v1 * sn, im = v0 * sn + v1 * cc;
                        *(__half2*)(dsth + idx) = __floats2half2_rn(re, im);
                    } else {
                        *(__half2*)(g_Vh + idx) = __floats2half2_rn(v0, v1);
                    }
                }
}

// ---------------- LSE + w + scaled wV fused; persistent-Q, K=64 slabs ----------------
// smem: [0,32768) Q persistent; [32768,81920) K ring 3x16KB;
//       [81920,82432) diag; [82432,83456) tmp; [83456,83968) wrow
#define L_SMEM 83968

__global__ __launch_bounds__(256, 2) void lse_mma() {
    extern __shared__ __align__(16) char smem[];
    const uint32_t sQ = smem_u32(smem);
    const uint32_t sK = sQ + 32768u;
    float* diag = (float*)(smem + 81920);
    float* tmp  = (float*)(smem + 82432);
    float* wrow = (float*)(smem + 83456);
    const int tid = threadIdx.x, w = tid >> 5, lane = tid & 31;
    const int wm = w & 3, wn = w >> 2;
    const int q0 = blockIdx.x * 128, h = blockIdx.y, b = blockIdx.z;
    const float scale = 0.08838834764831845f;
    const size_t qbase = (((size_t)(b * Ssz + q0)) << 11) + h * DHsz;
    const size_t kbb   = (((size_t)(b * Ssz)) << 11) + h * DHsz;

    uint32_t doff[4];
    const __half* pK[4];
#pragma unroll
    for (int i = 0; i < 4; i++) {
        int u = tid + (i << 8);
        int r = u >> 3, ch = u & 7;
        doff[i] = (uint32_t)(r * 128 + ((ch ^ (r & 7)) << 4));
        pK[i] = g_Kh + kbb + ((size_t)r << 11) + ch * 8;
    }

    // persistent Q
#pragma unroll
    for (int i = 0; i < 8; i++) {
        int u = tid + i * 256;
        int r = u >> 4, ch = u & 15;
        CP16(sQ + (uint32_t)(r * 256 + ((ch ^ (r & 7)) << 4)),
             g_Qh + qbase + ((size_t)r << 11) + ch * 8);
    }
    CP_COMMIT();

    const uint32_t lanehi4 = (uint32_t)((lane >> 4) << 4);
    uint32_t baseQ[2], baseK[4];
    {
        int rA0 = wm * 32 + (lane & 15);
#pragma unroll
        for (int mi = 0; mi < 2; mi++) {
            int r = rA0 + mi * 16;
            baseQ[mi] = (uint32_t)(r * 256 + ((r & 7) << 4));
        }
#pragma unroll
        for (int nb = 0; nb < 4; nb++) {
            int r = wn * 64 + nb * 16 + (lane & 15);
            baseK[nb] = (uint32_t)(r * 128 + ((r & 7) << 4));
        }
    }

    const int NS = 32;
#define L_ISSUE(bix, par) do {                                                 \
        uint32_t _bk = sK + (uint32_t)(bix) * KBUF;                            \
        size_t _adv = (par) ? (size_t)(128 * 2048 - 64) : (size_t)64;          \
        _Pragma("unroll")                                                      \
        for (int _i = 0; _i < 4; _i++) {                                       \
            CP16(_bk + doff[_i], pK[_i]);                                      \
            pK[_i] += _adv;                                                    \
        }                                                                      \
        CP_COMMIT();                                                            \
    } while (0)

    L_ISSUE(0, 0);
    L_ISSUE(1, 1);

    float acc[64];
#pragma unroll
    for (int i = 0; i < 64; i++) acc[i] = 0.f;
    float rsacc[4] = {0.f, 0.f, 0.f, 0.f};
    const int l4 = lane >> 2, lm = lane & 3;

    int bi = 0, ii = 2, j = 0, cnum = 0;
    for (int s = 0; s < NS; s++) {
        if (s + 1 < NS) CP_WAIT1(); else CP_WAIT0();
        __syncthreads();
        if (s + 2 < NS) {
            L_ISSUE(ii, s & 1);
            ii = (ii == 2) ? 0 : ii + 1;
        }
        uint32_t bufK = sK + (uint32_t)bi * KBUF;
        bi = (bi == 2) ? 0 : bi + 1;
        const uint32_t jbit = (uint32_t)(j << 7);

        uint32_t am[2][4], bm[2][4][4];
        // preload K fragments for ks=0
#pragma unroll
        for (int nb = 0; nb < 4; nb++)
            ldsm4(bm[0][nb], bufK + (baseK[nb] ^ lanehi4));
#pragma unroll
        for (int ks = 0; ks < 4; ks++) {
            uint32_t cbx = (uint32_t)(ks << 5) | lanehi4;
            uint32_t qx  = cbx | jbit;
#pragma unroll
            for (int mi = 0; mi < 2; mi++)
                ldsm4(am[mi], sQ + (baseQ[mi] ^ qx));
            if (ks < 3) {
                uint32_t cbn = (uint32_t)((ks + 1) << 5) | lanehi4;
#pragma unroll
                for (int nb = 0; nb < 4; nb++)
                    ldsm4(bm[(ks + 1) & 1][nb], bufK + (baseK[nb] ^ cbn));
            }
            const int c = ks & 1;
#pragma unroll
            for (int mi = 0; mi < 2; mi++)
#pragma unroll
                for (int nb = 0; nb < 4; nb++) {
                    mma16816(&acc[(mi * 8 + nb * 2 + 0) * 4], am[mi], bm[c][nb][0], bm[c][nb][2]);
                    mma16816(&acc[(mi * 8 + nb * 2 + 1) * 4], am[mi], bm[c][nb][1], bm[c][nb][3]);
                }
        }
        if (++j == 2) {   // key chunk complete
            j = 0;
#pragma unroll
            for (int mi = 0; mi < 2; mi++)
#pragma unroll
                for (int rh = 0; rh < 2; rh++) {
                    float pp = 0.f;
#pragma unroll
                    for (int nb = 0; nb < 4; nb++)
#pragma unroll
                        for (int jj = 0; jj < 2; jj++) {
                            pp += __expf(acc[(mi * 8 + nb * 2 + jj) * 4 + rh * 2 + 0] * scale);
                            pp += __expf(acc[(mi * 8 + nb * 2 + jj) * 4 + rh * 2 + 1] * scale);
                        }
                    rsacc[mi * 2 + rh] += pp;
                }
            if (cnum == (int)blockIdx.x) {   // diagonal chunk
#pragma unroll
                for (int mi = 0; mi < 2; mi++)
#pragma unroll
                    for (int nb = 0; nb < 4; nb++)
#pragma unroll
                        for (int jj = 0; jj < 2; jj++)
#pragma unroll
                            for (int rh = 0; rh < 2; rh++) {
                                int row = wm * 32 + mi * 16 + l4 + rh * 8;
                                int col = wn * 64 + nb * 16 + jj * 8 + lm * 2;
                                if (row == col)
                                    diag[row] = acc[(mi * 8 + nb * 2 + jj) * 4 + rh * 2 + 0];
                                if (row == col + 1)
                                    diag[row] = acc[(mi * 8 + nb * 2 + jj) * 4 + rh * 2 + 1];
                            }
            }
            cnum++;
#pragma unroll
            for (int i = 0; i < 64; i++) acc[i] = 0.f;
        }
    }

    // rowsum reduce -> w in smem
#pragma unroll
    for (int i = 0; i < 4; i++) {
        rsacc[i] += __shfl_xor_sync(0xffffffffu, rsacc[i], 1);
        rsacc[i] += __shfl_xor_sync(0xffffffffu, rsacc[i], 2);
    }
    if (lm == 0) {
#pragma unroll
        for (int mi = 0; mi < 2; mi++)
#pragma unroll
            for (int rh = 0; rh < 2; rh++)
                tmp[wn * 128 + wm * 32 + mi * 16 + rh * 8 + l4] = rsacc[mi * 2 + rh];
    }
    __syncthreads();
    if (tid < 128) {
        float sum = tmp[tid] + tmp[128 + tid];
        wrow[tid] = __expf(diag[tid] * scale - logf(sum)) * ASCALE;
    }
    __syncthreads();

    // fused scaled wV
#pragma unroll
    for (int i = 0; i < 8; i++) {
        int u = tid + i * 256;
        int r = u >> 4, ch = u & 15;
        size_t idx = (((size_t)(b * Ssz + q0 + r)) << 11) + h * DHsz + ch * 8;
        float wv = wrow[r];
        __half2 vin[4];
        *(uint4*)vin = *(const uint4*)(g_Vh + idx);
        __half2 vout[4];
#pragma unroll
        for (int q = 0; q < 4; q++) {
            float2 f = __half22float2(vin[q]);
            vout[q] = __floats2half2_rn(f.x * wv, f.y * wv);
        }
        *(uint4*)(g_Ah + idx) = *(uint4*)vout;
    }
}

// ---------------- launch ----------------
extern "C" void kernel_launch(void* const* d_in, const int* in_sizes, int n_in,
                              void* d_out, int out_size) {
    const float* x  = (const float*)d_in[0];
    const float* rc = (const float*)d_in[1];
    const float* rs = (const float*)d_in[2];
    const float* Wq = (const float*)d_in[3];
    const float* Wk = (const float*)d_in[4];
    const float* Wv = (const float*)d_in[5];
    const float* Wo = (const float*)d_in[6];
    float* out = (float*)d_out;

    cudaFuncSetAttribute(gemm_mma, cudaFuncAttributeMaxDynamicSharedMemorySize, G_SMEM);
    cudaFuncSetAttribute(lse_mma, cudaFuncAttributeMaxDynamicSharedMemorySize, L_SMEM);

    conv_all<<<(XCHUNKS + 4 * WCHUNKS) / 256, 256>>>(x, Wq, Wk, Wv, Wo);      // 1
    gemm_mma<<<dim3(Msz / 128, 48), 256, G_SMEM>>>(rc, rs, nullptr, 0);       // 2: QKV merged
    lse_mma<<<dim3(Ssz / 128, Hn, Bsz), 256, L_SMEM>>>();                     // 3: lse+w+A
    gemm_mma<<<dim3(Msz / 128, Dsz / 128), 256, G_SMEM>>>(rc, rs, out, 3);    // 4: A@Wo^T
}

// round 16
// speedup vs baseline: 1.0080x; 1.0080x over previous
#include <cuda_runtime.h>
#include <cuda_fp16.h>
#include <cstdint>

#define Bsz 2
#define Ssz 2048
#define Dsz 2048
#define Hn 16
#define DHsz 128
#define Msz (Bsz*Ssz)

__device__ __align__(16) __half g_xh[(size_t)Msz*Dsz];
__device__ __align__(16) __half g_Wh[4][(size_t)Dsz*Dsz];
__device__ __align__(16) __half g_Qh[(size_t)Msz*Dsz];
__device__ __align__(16) __half g_Kh[(size_t)Msz*Dsz];
__device__ __align__(16) __half g_Vh[(size_t)Msz*Dsz];
__device__ __align__(16) __half g_Ah[(size_t)Msz*Dsz];   // 1024 * w * V

#define ASCALE 1024.0f
#define AINV   0.0009765625f

__device__ __forceinline__ uint32_t smem_u32(const void* p) {
    uint32_t a;
    asm("{ .reg .u64 t; cvta.to.shared.u64 t, %1; cvt.u32.u64 %0, t; }" : "=r"(a) : "l"(p));
    return a;
}
__device__ __forceinline__ void ldsm4(uint32_t* r, uint32_t a) {
    asm volatile("ldmatrix.sync.aligned.m8n8.x4.shared.b16 {%0,%1,%2,%3}, [%4];"
                 : "=r"(r[0]), "=r"(r[1]), "=r"(r[2]), "=r"(r[3]) : "r"(a));
}
__device__ __forceinline__ void mma16816(float* c, const uint32_t* a, uint32_t b0, uint32_t b1) {
    asm volatile("mma.sync.aligned.m16n8k16.row.col.f32.f16.f16.f32 "
                 "{%0,%1,%2,%3},{%4,%5,%6,%7},{%8,%9},{%0,%1,%2,%3};"
                 : "+f"(c[0]), "+f"(c[1]), "+f"(c[2]), "+f"(c[3])
                 : "r"(a[0]), "r"(a[1]), "r"(a[2]), "r"(a[3]), "r"(b0), "r"(b1));
}
#define CP16(dst, src) asm volatile("cp.async.cg.shared.global [%0], [%1], 16;" :: "r"(dst), "l"(src))
#define CP_COMMIT()    asm volatile("cp.async.commit_group;" ::: "memory")
#define CP_WAIT1()     asm volatile("cp.async.wait_group 1;" ::: "memory")
#define CP_WAIT0()     asm volatile("cp.async.wait_group 0;" ::: "memory")

// ---------------- single fused fp32 -> fp16 conversion (x + all 4 W) ----------------
#define XCHUNKS 1048576   // Msz*Dsz/8
#define WCHUNKS 524288    // Dsz*Dsz/8

__global__ __launch_bounds__(256) void conv_all(const float* __restrict__ x,
                                                const float* __restrict__ w0,
                                                const float* __restrict__ w1,
                                                const float* __restrict__ w2,
                                                const float* __restrict__ w3) {
    int i = blockIdx.x * 256 + threadIdx.x;
    const float* src;
    __half* dst;
    size_t off;
    if (i < XCHUNKS) {
        src = x; dst = g_xh; off = (size_t)i * 8;
    } else {
        int r = i - XCHUNKS;
        int sel = r >> 19;
        off = (size_t)(r & (WCHUNKS - 1)) * 8;
        src = (sel == 0) ? w0 : (sel == 1) ? w1 : (sel == 2) ? w2 : w3;
        dst = g_Wh[sel];
    }
    float4 v0 = *(const float4*)(src + off);
    float4 v1 = *(const float4*)(src + off + 4);
    __half2 h[4];
    h[0] = __floats2half2_rn(v0.x, v0.y);
    h[1] = __floats2half2_rn(v0.z, v0.w);
    h[2] = __floats2half2_rn(v1.x, v1.y);
    h[3] = __floats2half2_rn(v1.z, v1.w);
    *(uint4*)(dst + off) = *(uint4*)h;
}

// ---------------- GEMM: 1-pass fp16, K=64 slabs, 3-stage cp.async ----------------
#define KBUF 16384u
#define G_SMEM 98304

__global__ __launch_bounds__(256, 2) void gemm_mma(const float* __restrict__ rc,
                                                   const float* __restrict__ rs,
                                                   float* __restrict__ Co, int mode) {
    extern __shared__ __align__(16) char smem[];
    const int tid = threadIdx.x, w = tid >> 5, lane = tid & 31;
    const int wm = w & 3, wn = w >> 2;
    const int m0 = blockIdx.x * 128;
    const int wsel = (mode == 3) ? 3 : (blockIdx.y >> 4);
    const int n0 = (mode == 3) ? blockIdx.y * 128 : (blockIdx.y & 15) * 128;
    const __half* Ah = (mode == 3) ? g_Ah : g_xh;
    const __half* Bh = g_Wh[wsel];

    float acc[64];
#pragma unroll
    for (int i = 0; i < 64; i++) acc[i] = 0.f;

    const uint32_t sA = smem_u32(smem), sB = sA + 3 * KBUF;
    uint32_t doff[4];
    const __half* pA[4];
    const __half* pB[4];
#pragma unroll
    for (int i = 0; i < 4; i++) {
        int u = tid + (i << 8);
        int r = u >> 3, ch = u & 7;
        doff[i] = (uint32_t)(r * 128 + ((ch ^ (r & 7)) << 4));
        pA[i] = Ah + (size_t)(m0 + r) * Dsz + ch * 8;
        pB[i] = Bh + (size_t)(n0 + r) * Dsz + ch * 8;
    }
    const uint32_t lanehi4 = (uint32_t)((lane >> 4) << 4);
    uint32_t baseA[2], baseB[4];
    {
        int rA0 = wm * 32 + (lane & 15);
#pragma unroll
        for (int mi = 0; mi < 2; mi++) {
            int r = rA0 + mi * 16;
            baseA[mi] = (uint32_t)(r * 128 + ((r & 7) << 4));
        }
#pragma unroll
        for (int nb = 0; nb < 4; nb++) {
            int r = wn * 64 + nb * 16 + (lane & 15);
            baseB[nb] = (uint32_t)(r * 128 + ((r & 7) << 4));
        }
    }
    const int NS = 32;

#define G_ISSUE(bi) do {                                                       \
        uint32_t _ba = sA + (uint32_t)(bi) * KBUF;                             \
        uint32_t _bb = sB + (uint32_t)(bi) * KBUF;                             \
        _Pragma("unroll")                                                      \
        for (int _i = 0; _i < 4; _i++) {                                       \
            CP16(_ba + doff[_i], pA[_i]);                                      \
            CP16(_bb + doff[_i], pB[_i]);                                      \
            pA[_i] += 64; pB[_i] += 64;                                        \
        }                                                                      \
        CP_COMMIT();                                                            \
    } while (0)

#define G_KSTEP(ks) do {                                                       \
        uint32_t cbx = (uint32_t)((ks) << 5) | lanehi4;                        \
        uint32_t am[2][4], bm[4][4];                                           \
        _Pragma("unroll")                                                      \
        for (int mi = 0; mi < 2; mi++)                                         \
            ldsm4(am[mi], bufA + (baseA[mi] ^ cbx));                           \
        _Pragma("unroll")                                                      \
        for (int nb = 0; nb < 4; nb++)                                         \
            ldsm4(bm[nb], bufB + (baseB[nb] ^ cbx));                           \
        _Pragma("unroll")                                                      \
        for (int mi = 0; mi < 2; mi++)                                         \
            _Pragma("unroll")                                                  \
            for (int nb = 0; nb < 4; nb++) {                                   \
                mma16816(&acc[(mi * 8 + nb * 2 + 0) * 4], am[mi], bm[nb][0], bm[nb][2]); \
                mma16816(&acc[(mi * 8 + nb * 2 + 1) * 4], am[mi], bm[nb][1], bm[nb][3]); \
            }                                                                  \
    } while (0)

    G_ISSUE(0);
    G_ISSUE(1);

    int bi = 0, ii = 2;
    for (int s = 0; s < NS; s++) {
        if (s + 1 < NS) CP_WAIT1(); else CP_WAIT0();
        __syncthreads();
        uint32_t bufA = sA + (uint32_t)bi * KBUF;
        uint32_t bufB = sB + (uint32_t)bi * KBUF;
        bi = (bi == 2) ? 0 : bi + 1;
        G_KSTEP(0);
        G_KSTEP(1);
        if (s + 2 < NS) {          // mid-slab issue: LSU work under MMA shadow
            G_ISSUE(ii);
            ii = (ii == 2) ? 0 : ii + 1;
        }
        G_KSTEP(2);
        G_KSTEP(3);
    }

    // epilogue
    const int l4 = lane >> 2, lm = lane & 3;
    __half* dsth = (wsel == 0) ? g_Qh : (wsel == 1) ? g_Kh : g_Vh;
#pragma unroll
    for (int mi = 0; mi < 2; mi++)
#pragma unroll
        for (int nb = 0; nb < 4; nb++)
#pragma unroll
            for (int j = 0; j < 2; j++)
#pragma unroll
                for (int rh = 0; rh < 2; rh++) {
                    float v0 = acc[(mi * 8 + nb * 2 + j) * 4 + rh * 2 + 0];
                    float v1 = acc[(mi * 8 + nb * 2 + j) * 4 + rh * 2 + 1];
                    int row = m0 + wm * 32 + mi * 16 + l4 + rh * 8;
                    int col = n0 + wn * 64 + nb * 16 + j * 8 + lm * 2;
                    size_t idx = ((size_t)row << 11) + col;
                    if (mode == 3) {
                        *(float2*)(Co + idx) = make_float2(v0 * AINV, v1 * AINV);
                    } else if (wsel <= 1) {
                        int p = (col & 127) >> 1, srow = row & (Ssz - 1);
                        float cc = rc[srow * 64 + p], sn = rs[srow * 64 + p];
                        float re = v0 * cc - v1 * sn, im = v0 * sn + v1 * cc;
                        *(__half2*)(dsth + idx) = __floats2half2_rn(re, im);
                    } else {
                        *(__half2*)(g_Vh + idx) = __floats2half2_rn(v0, v1);
                    }
                }
}

// ---------------- LSE + w + scaled wV fused; persistent-Q, K=64 slabs ----------------
// smem: [0,32768) Q persistent; [32768,81920) K ring 3x16KB;
//       [81920,82432) diag; [82432,83456) tmp; [83456,83968) wrow
#define L_SMEM 83968

__global__ __launch_bounds__(256, 2) void lse_mma() {
    extern __shared__ __align__(16) char smem[];
    const uint32_t sQ = smem_u32(smem);
    const uint32_t sK = sQ + 32768u;
    float* diag = (float*)(smem + 81920);
    float* tmp  = (float*)(smem + 82432);
    float* wrow = (float*)(smem + 83456);
    const int tid = threadIdx.x, w = tid >> 5, lane = tid & 31;
    const int wm = w & 3, wn = w >> 2;
    const int q0 = blockIdx.x * 128, h = blockIdx.y, b = blockIdx.z;
    const float scale = 0.08838834764831845f;
    const size_t qbase = (((size_t)(b * Ssz + q0)) << 11) + h * DHsz;
    const size_t kbb   = (((size_t)(b * Ssz)) << 11) + h * DHsz;

    uint32_t doff[4];
    const __half* pK[4];
#pragma unroll
    for (int i = 0; i < 4; i++) {
        int u = tid + (i << 8);
        int r = u >> 3, ch = u & 7;
        doff[i] = (uint32_t)(r * 128 + ((ch ^ (r & 7)) << 4));
        pK[i] = g_Kh + kbb + ((size_t)r << 11) + ch * 8;
    }

    // persistent Q
#pragma unroll
    for (int i = 0; i < 8; i++) {
        int u = tid + i * 256;
        int r = u >> 4, ch = u & 15;
        CP16(sQ + (uint32_t)(r * 256 + ((ch ^ (r & 7)) << 4)),
             g_Qh + qbase + ((size_t)r << 11) + ch * 8);
    }
    CP_COMMIT();

    const uint32_t lanehi4 = (uint32_t)((lane >> 4) << 4);
    uint32_t baseQ[2], baseK[4];
    {
        int rA0 = wm * 32 + (lane & 15);
#pragma unroll
        for (int mi = 0; mi < 2; mi++) {
            int r = rA0 + mi * 16;
            baseQ[mi] = (uint32_t)(r * 256 + ((r & 7) << 4));
        }
#pragma unroll
        for (int nb = 0; nb < 4; nb++) {
            int r = wn * 64 + nb * 16 + (lane & 15);
            baseK[nb] = (uint32_t)(r * 128 + ((r & 7) << 4));
        }
    }

    const int NS = 32;
#define L_ISSUE(bix, par) do {                                                 \
        uint32_t _bk = sK + (uint32_t)(bix) * KBUF;                            \
        size_t _adv = (par) ? (size_t)(128 * 2048 - 64) : (size_t)64;          \
        _Pragma("unroll")                                                      \
        for (int _i = 0; _i < 4; _i++) {                                       \
            CP16(_bk + doff[_i], pK[_i]);                                      \
            pK[_i] += _adv;                                                    \
        }                                                                      \
        CP_COMMIT();                                                            \
    } while (0)

#define L_KSTEP(ks) do {                                                       \
        uint32_t cbx = (uint32_t)((ks) << 5) | lanehi4;                        \
        uint32_t qx  = cbx | jbit;                                             \
        uint32_t am[2][4], bm[4][4];                                           \
        _Pragma("unroll")                                                      \
        for (int mi = 0; mi < 2; mi++)                                         \
            ldsm4(am[mi], sQ + (baseQ[mi] ^ qx));                              \
        _Pragma("unroll")                                                      \
        for (int nb = 0; nb < 4; nb++)                                         \
            ldsm4(bm[nb], bufK + (baseK[nb] ^ cbx));                           \
        _Pragma("unroll")                                                      \
        for (int mi = 0; mi < 2; mi++)                                         \
            _Pragma("unroll")                                                  \
            for (int nb = 0; nb < 4; nb++) {                                   \
                mma16816(&acc[(mi * 8 + nb * 2 + 0) * 4], am[mi], bm[nb][0], bm[nb][2]); \
                mma16816(&acc[(mi * 8 + nb * 2 + 1) * 4], am[mi], bm[nb][1], bm[nb][3]); \
            }                                                                  \
    } while (0)

    L_ISSUE(0, 0);
    L_ISSUE(1, 1);

    float acc[64];
#pragma unroll
    for (int i = 0; i < 64; i++) acc[i] = 0.f;
    float rsacc[4] = {0.f, 0.f, 0.f, 0.f};
    const int l4 = lane >> 2, lm = lane & 3;

    int bi = 0, ii = 2, j = 0, cnum = 0;
    for (int s = 0; s < NS; s++) {
        if (s + 1 < NS) CP_WAIT1(); else CP_WAIT0();
        __syncthreads();
        uint32_t bufK = sK + (uint32_t)bi * KBUF;
        bi = (bi == 2) ? 0 : bi + 1;
        const uint32_t jbit = (uint32_t)(j << 7);
        L_KSTEP(0);
        L_KSTEP(1);
        if (s + 2 < NS) {          // mid-slab issue
            L_ISSUE(ii, s & 1);
            ii = (ii == 2) ? 0 : ii + 1;
        }
        L_KSTEP(2);
        L_KSTEP(3);
        if (++j == 2) {   // key chunk complete
            j = 0;
#pragma unroll
            for (int mi = 0; mi < 2; mi++)
#pragma unroll
                for (int rh = 0; rh < 2; rh++) {
                    float pp = 0.f;
#pragma unroll
                    for (int nb = 0; nb < 4; nb++)
#pragma unroll
                        for (int jj = 0; jj < 2; jj++) {
                            pp += __expf(acc[(mi * 8 + nb * 2 + jj) * 4 + rh * 2 + 0] * scale);
                            pp += __expf(acc[(mi * 8 + nb * 2 + jj) * 4 + rh * 2 + 1] * scale);
                        }
                    rsacc[mi * 2 + rh] += pp;
                }
            if (cnum == (int)blockIdx.x) {   // diagonal chunk
#pragma unroll
                for (int mi = 0; mi < 2; mi++)
#pragma unroll
                    for (int nb = 0; nb < 4; nb++)
#pragma unroll
                        for (int jj = 0; jj < 2; jj++)
#pragma unroll
                            for (int rh = 0; rh < 2; rh++) {
                                int row = wm * 32 + mi * 16 + l4 + rh * 8;
                                int col = wn * 64 + nb * 16 + jj * 8 + lm * 2;
                                if (row == col)
                                    diag[row] = acc[(mi * 8 + nb * 2 + jj) * 4 + rh * 2 + 0];
                                if (row == col + 1)
                                    diag[row] = acc[(mi * 8 + nb * 2 + jj) * 4 + rh * 2 + 1];
                            }
            }
            cnum++;
#pragma unroll
            for (int i = 0; i < 64; i++) acc[i] = 0.f;
        }
    }

    // rowsum reduce -> w in smem
#pragma unroll
    for (int i = 0; i < 4; i++) {
        rsacc[i] += __shfl_xor_sync(0xffffffffu, rsacc[i], 1);
        rsacc[i] += __shfl_xor_sync(0xffffffffu, rsacc[i], 2);
    }
    if (lm == 0) {
#pragma unroll
        for (int mi = 0; mi < 2; mi++)
#pragma unroll
            for (int rh = 0; rh < 2; rh++)
                tmp[wn * 128 + wm * 32 + mi * 16 + rh * 8 + l4] = rsacc[mi * 2 + rh];
    }
    __syncthreads();
    if (tid < 128) {
        float sum = tmp[tid] + tmp[128 + tid];
        wrow[tid] = __expf(diag[tid] * scale - logf(sum)) * ASCALE;
    }
    __syncthreads();

    // fused scaled wV
#pragma unroll
    for (int i = 0; i < 8; i++) {
        int u = tid + i * 256;
        int r = u >> 4, ch = u & 15;
        size_t idx = (((size_t)(b * Ssz + q0 + r)) << 11) + h * DHsz + ch * 8;
        float wv = wrow[r];
        __half2 vin[4];
        *(uint4*)vin = *(const uint4*)(g_Vh + idx);
        __half2 vout[4];
#pragma unroll
        for (int q = 0; q < 4; q++) {
            float2 f = __half22float2(vin[q]);
            vout[q] = __floats2half2_rn(f.x * wv, f.y * wv);
        }
        *(uint4*)(g_Ah + idx) = *(uint4*)vout;
    }
}

// ---------------- launch ----------------
extern "C" void kernel_launch(void* const* d_in, const int* in_sizes, int n_in,
                              void* d_out, int out_size) {
    const float* x  = (const float*)d_in[0];
    const float* rc = (const float*)d_in[1];
    const float* rs = (const float*)d_in[2];
    const float* Wq = (const float*)d_in[3];
    const float* Wk = (const float*)d_in[4];
    const float* Wv = (const float*)d_in[5];
    const float* Wo = (const float*)d_in[6];
    float* out = (float*)d_out;

    cudaFuncSetAttribute(gemm_mma, cudaFuncAttributeMaxDynamicSharedMemorySize, G_SMEM);
    cudaFuncSetAttribute(lse_mma, cudaFuncAttributeMaxDynamicSharedMemorySize, L_SMEM);

    conv_all<<<(XCHUNKS + 4 * WCHUNKS) / 256, 256>>>(x, Wq, Wk, Wv, Wo);      // 1
    gemm_mma<<<dim3(Msz / 128, 48), 256, G_SMEM>>>(rc, rs, nullptr, 0);       // 2: QKV merged
    lse_mma<<<dim3(Ssz / 128, Hn, Bsz), 256, L_SMEM>>>();                     // 3: lse+w+A
    gemm_mma<<<dim3(Msz / 128, Dsz / 128), 256, G_SMEM>>>(rc, rs, out, 3);    // 4: A@Wo^T
}

// round 17
// speedup vs baseline: 1.0717x; 1.0632x over previous
#include <cuda_runtime.h>
#include <cuda_fp16.h>
#include <cstdint>

#define Bsz 2
#define Ssz 2048
#define Dsz 2048
#define Hn 16
#define DHsz 128
#define Msz (Bsz*Ssz)

__device__ __align__(16) __half g_xh[(size_t)Msz*Dsz];
__device__ __align__(16) __half g_Wh[4][(size_t)Dsz*Dsz];
__device__ __align__(16) __half g_Qh[(size_t)Msz*Dsz];
__device__ __align__(16) __half g_Kh[(size_t)Msz*Dsz];
__device__ __align__(16) __half g_Vh[(size_t)Msz*Dsz];
__device__ __align__(16) __half g_Ah[(size_t)Msz*Dsz];   // 1024 * w * V

#define ASCALE 1024.0f
#define AINV   0.0009765625f
#define SC_LOG2E 0.12751744486873f   // DH^-0.5 * log2(e)

__device__ __forceinline__ uint32_t smem_u32(const void* p) {
    uint32_t a;
    asm("{ .reg .u64 t; cvta.to.shared.u64 t, %1; cvt.u32.u64 %0, t; }" : "=r"(a) : "l"(p));
    return a;
}
__device__ __forceinline__ void ldsm4(uint32_t* r, uint32_t a) {
    asm volatile("ldmatrix.sync.aligned.m8n8.x4.shared.b16 {%0,%1,%2,%3}, [%4];"
                 : "=r"(r[0]), "=r"(r[1]), "=r"(r[2]), "=r"(r[3]) : "r"(a));
}
__device__ __forceinline__ void mma16816(float* c, const uint32_t* a, uint32_t b0, uint32_t b1) {
    asm volatile("mma.sync.aligned.m16n8k16.row.col.f32.f16.f16.f32 "
                 "{%0,%1,%2,%3},{%4,%5,%6,%7},{%8,%9},{%0,%1,%2,%3};"
                 : "+f"(c[0]), "+f"(c[1]), "+f"(c[2]), "+f"(c[3])
                 : "r"(a[0]), "r"(a[1]), "r"(a[2]), "r"(a[3]), "r"(b0), "r"(b1));
}
// two exponentials per MUFU op: exp(x0*s), exp(x1*s) via ex2.approx.f16x2
__device__ __forceinline__ float exp2pair(float x0, float x1) {
    uint32_t hx, he;
    asm("cvt.rn.f16x2.f32 %0, %1, %2;" : "=r"(hx) : "f"(x1 * SC_LOG2E), "f"(x0 * SC_LOG2E));
    asm("ex2.approx.f16x2 %0, %1;" : "=r"(he) : "r"(hx));
    __half2 h = *(__half2*)&he;
    float2 f = __half22float2(h);
    return f.x + f.y;
}
#define CP16(dst, src) asm volatile("cp.async.cg.shared.global [%0], [%1], 16;" :: "r"(dst), "l"(src))
#define CP_COMMIT()    asm volatile("cp.async.commit_group;" ::: "memory")
#define CP_WAIT1()     asm volatile("cp.async.wait_group 1;" ::: "memory")
#define CP_WAIT0()     asm volatile("cp.async.wait_group 0;" ::: "memory")

// ---------------- single fused fp32 -> fp16 conversion (x + all 4 W) ----------------
#define XCHUNKS 1048576   // Msz*Dsz/8
#define WCHUNKS 524288    // Dsz*Dsz/8

__global__ __launch_bounds__(256) void conv_all(const float* __restrict__ x,
                                                const float* __restrict__ w0,
                                                const float* __restrict__ w1,
                                                const float* __restrict__ w2,
                                                const float* __restrict__ w3) {
    int i = blockIdx.x * 256 + threadIdx.x;
    const float* src;
    __half* dst;
    size_t off;
    if (i < XCHUNKS) {
        src = x; dst = g_xh; off = (size_t)i * 8;
    } else {
        int r = i - XCHUNKS;
        int sel = r >> 19;
        off = (size_t)(r & (WCHUNKS - 1)) * 8;
        src = (sel == 0) ? w0 : (sel == 1) ? w1 : (sel == 2) ? w2 : w3;
        dst = g_Wh[sel];
    }
    float4 v0 = *(const float4*)(src + off);
    float4 v1 = *(const float4*)(src + off + 4);
    __half2 h[4];
    h[0] = __floats2half2_rn(v0.x, v0.y);
    h[1] = __floats2half2_rn(v0.z, v0.w);
    h[2] = __floats2half2_rn(v1.x, v1.y);
    h[3] = __floats2half2_rn(v1.z, v1.w);
    *(uint4*)(dst + off) = *(uint4*)h;
}

// ---------------- GEMM (round-12 exact): 1-pass fp16, K=64 slabs, 3-stage cp.async ----------------
#define KBUF 16384u
#define G_SMEM 98304

__global__ __launch_bounds__(256, 2) void gemm_mma(const float* __restrict__ rc,
                                                   const float* __restrict__ rs,
                                                   float* __restrict__ Co, int mode) {
    extern __shared__ __align__(16) char smem[];
    const int tid = threadIdx.x, w = tid >> 5, lane = tid & 31;
    const int wm = w & 3, wn = w >> 2;
    const int m0 = blockIdx.x * 128;
    const int wsel = (mode == 3) ? 3 : (blockIdx.y >> 4);
    const int n0 = (mode == 3) ? blockIdx.y * 128 : (blockIdx.y & 15) * 128;
    const __half* Ah = (mode == 3) ? g_Ah : g_xh;
    const __half* Bh = g_Wh[wsel];

    float acc[64];
#pragma unroll
    for (int i = 0; i < 64; i++) acc[i] = 0.f;

    const uint32_t sA = smem_u32(smem), sB = sA + 3 * KBUF;
    uint32_t doff[4];
    const __half* pA[4];
    const __half* pB[4];
#pragma unroll
    for (int i = 0; i < 4; i++) {
        int u = tid + (i << 8);
        int r = u >> 3, ch = u & 7;
        doff[i] = (uint32_t)(r * 128 + ((ch ^ (r & 7)) << 4));
        pA[i] = Ah + (size_t)(m0 + r) * Dsz + ch * 8;
        pB[i] = Bh + (size_t)(n0 + r) * Dsz + ch * 8;
    }
    const uint32_t lanehi4 = (uint32_t)((lane >> 4) << 4);
    uint32_t baseA[2], baseB[4];
    {
        int rA0 = wm * 32 + (lane & 15);
#pragma unroll
        for (int mi = 0; mi < 2; mi++) {
            int r = rA0 + mi * 16;
            baseA[mi] = (uint32_t)(r * 128 + ((r & 7) << 4));
        }
#pragma unroll
        for (int nb = 0; nb < 4; nb++) {
            int r = wn * 64 + nb * 16 + (lane & 15);
            baseB[nb] = (uint32_t)(r * 128 + ((r & 7) << 4));
        }
    }
    const int NS = 32;

#define G_ISSUE(bi) do {                                                       \
        uint32_t _ba = sA + (uint32_t)(bi) * KBUF;                             \
        uint32_t _bb = sB + (uint32_t)(bi) * KBUF;                             \
        _Pragma("unroll")                                                      \
        for (int _i = 0; _i < 4; _i++) {                                       \
            CP16(_ba + doff[_i], pA[_i]);                                      \
            CP16(_bb + doff[_i], pB[_i]);                                      \
            pA[_i] += 64; pB[_i] += 64;                                        \
        }                                                                      \
        CP_COMMIT();                                                            \
    } while (0)

    G_ISSUE(0);
    G_ISSUE(1);

    int bi = 0, ii = 2;
    for (int s = 0; s < NS; s++) {
        if (s + 1 < NS) CP_WAIT1(); else CP_WAIT0();
        __syncthreads();
        if (s + 2 < NS) {
            G_ISSUE(ii);
            ii = (ii == 2) ? 0 : ii + 1;
        }
        uint32_t bufA = sA + (uint32_t)bi * KBUF;
        uint32_t bufB = sB + (uint32_t)bi * KBUF;
        bi = (bi == 2) ? 0 : bi + 1;
#pragma unroll
        for (int ks = 0; ks < 4; ks++) {
            uint32_t cbx = (uint32_t)(ks << 5) | lanehi4;
            uint32_t am[2][4], bm[4][4];
#pragma unroll
            for (int mi = 0; mi < 2; mi++)
                ldsm4(am[mi], bufA + (baseA[mi] ^ cbx));
#pragma unroll
            for (int nb = 0; nb < 4; nb++)
                ldsm4(bm[nb], bufB + (baseB[nb] ^ cbx));
#pragma unroll
            for (int mi = 0; mi < 2; mi++)
#pragma unroll
                for (int nb = 0; nb < 4; nb++) {
                    mma16816(&acc[(mi * 8 + nb * 2 + 0) * 4], am[mi], bm[nb][0], bm[nb][2]);
                    mma16816(&acc[(mi * 8 + nb * 2 + 1) * 4], am[mi], bm[nb][1], bm[nb][3]);
                }
        }
    }

    // epilogue
    const int l4 = lane >> 2, lm = lane & 3;
    __half* dsth = (wsel == 0) ? g_Qh : (wsel == 1) ? g_Kh : g_Vh;
#pragma unroll
    for (int mi = 0; mi < 2; mi++)
#pragma unroll
        for (int nb = 0; nb < 4; nb++)
#pragma unroll
            for (int j = 0; j < 2; j++)
#pragma unroll
                for (int rh = 0; rh < 2; rh++) {
                    float v0 = acc[(mi * 8 + nb * 2 + j) * 4 + rh * 2 + 0];
                    float v1 = acc[(mi * 8 + nb * 2 + j) * 4 + rh * 2 + 1];
                    int row = m0 + wm * 32 + mi * 16 + l4 + rh * 8;
                    int col = n0 + wn * 64 + nb * 16 + j * 8 + lm * 2;
                    size_t idx = ((size_t)row << 11) + col;
                    if (mode == 3) {
                        *(float2*)(Co + idx) = make_float2(v0 * AINV, v1 * AINV);
                    } else if (wsel <= 1) {
                        int p = (col & 127) >> 1, srow = row & (Ssz - 1);
                        float cc = rc[srow * 64 + p], sn = rs[srow * 64 + p];
                        float re = v0 * cc - v1 * sn, im = v0 * sn + v1 * cc;
                        *(__half2*)(dsth + idx) = __floats2half2_rn(re, im);
                    } else {
                        *(__half2*)(g_Vh + idx) = __floats2half2_rn(v0, v1);
                    }
                }
}

// ---------------- LSE + w + scaled wV fused; persistent-Q, K=64 slabs ----------------
// round-12 structure; exp via ex2.approx.f16x2 (2 exps per MUFU op)
// smem: [0,32768) Q persistent; [32768,81920) K ring 3x16KB;
//       [81920,82432) diag; [82432,83456) tmp; [83456,83968) wrow
#define L_SMEM 83968

__global__ __launch_bounds__(256, 2) void lse_mma() {
    extern __shared__ __align__(16) char smem[];
    const uint32_t sQ = smem_u32(smem);
    const uint32_t sK = sQ + 32768u;
    float* diag = (float*)(smem + 81920);
    float* tmp  = (float*)(smem + 82432);
    float* wrow = (float*)(smem + 83456);
    const int tid = threadIdx.x, w = tid >> 5, lane = tid & 31;
    const int wm = w & 3, wn = w >> 2;
    const int q0 = blockIdx.x * 128, h = blockIdx.y, b = blockIdx.z;
    const float scale = 0.08838834764831845f;
    const size_t qbase = (((size_t)(b * Ssz + q0)) << 11) + h * DHsz;
    const size_t kbb   = (((size_t)(b * Ssz)) << 11) + h * DHsz;

    uint32_t doff[4];
    const __half* pK[4];
#pragma unroll
    for (int i = 0; i < 4; i++) {
        int u = tid + (i << 8);
        int r = u >> 3, ch = u & 7;
        doff[i] = (uint32_t)(r * 128 + ((ch ^ (r & 7)) << 4));
        pK[i] = g_Kh + kbb + ((size_t)r << 11) + ch * 8;
    }

    // persistent Q
#pragma unroll
    for (int i = 0; i < 8; i++) {
        int u = tid + i * 256;
        int r = u >> 4, ch = u & 15;
        CP16(sQ + (uint32_t)(r * 256 + ((ch ^ (r & 7)) << 4)),
             g_Qh + qbase + ((size_t)r << 11) + ch * 8);
    }
    CP_COMMIT();

    const uint32_t lanehi4 = (uint32_t)((lane >> 4) << 4);
    uint32_t baseQ[2], baseK[4];
    {
        int rA0 = wm * 32 + (lane & 15);
#pragma unroll
        for (int mi = 0; mi < 2; mi++) {
            int r = rA0 + mi * 16;
            baseQ[mi] = (uint32_t)(r * 256 + ((r & 7) << 4));
        }
#pragma unroll
        for (int nb = 0; nb < 4; nb++) {
            int r = wn * 64 + nb * 16 + (lane & 15);
            baseK[nb] = (uint32_t)(r * 128 + ((r & 7) << 4));
        }
    }

    const int NS = 32;
#define L_ISSUE(bix, par) do {                                                 \
        uint32_t _bk = sK + (uint32_t)(bix) * KBUF;                            \
        size_t _adv = (par) ? (size_t)(128 * 2048 - 64) : (size_t)64;          \
        _Pragma("unroll")                                                      \
        for (int _i = 0; _i < 4; _i++) {                                       \
            CP16(_bk + doff[_i], pK[_i]);                                      \
            pK[_i] += _adv;                                                    \
        }                                                                      \
        CP_COMMIT();                                                            \
    } while (0)

    L_ISSUE(0, 0);
    L_ISSUE(1, 1);

    float acc[64];
#pragma unroll
    for (int i = 0; i < 64; i++) acc[i] = 0.f;
    float rsacc[4] = {0.f, 0.f, 0.f, 0.f};
    const int l4 = lane >> 2, lm = lane & 3;

    int bi = 0, ii = 2, j = 0, cnum = 0;
    for (int s = 0; s < NS; s++) {
        if (s + 1 < NS) CP_WAIT1(); else CP_WAIT0();
        __syncthreads();
        if (s + 2 < NS) {
            L_ISSUE(ii, s & 1);
            ii = (ii == 2) ? 0 : ii + 1;
        }
        uint32_t bufK = sK + (uint32_t)bi * KBUF;
        bi = (bi == 2) ? 0 : bi + 1;
        const uint32_t jbit = (uint32_t)(j << 7);
#pragma unroll
        for (int ks = 0; ks < 4; ks++) {
            uint32_t cbx = (uint32_t)(ks << 5) | lanehi4;
            uint32_t qx  = cbx | jbit;
            uint32_t am[2][4], bm[4][4];
#pragma unroll
            for (int mi = 0; mi < 2; mi++)
                ldsm4(am[mi], sQ + (baseQ[mi] ^ qx));
#pragma unroll
            for (int nb = 0; nb < 4; nb++)
                ldsm4(bm[nb], bufK + (baseK[nb] ^ cbx));
#pragma unroll
            for (int mi = 0; mi < 2; mi++)
#pragma unroll
                for (int nb = 0; nb < 4; nb++) {
                    mma16816(&acc[(mi * 8 + nb * 2 + 0) * 4], am[mi], bm[nb][0], bm[nb][2]);
                    mma16816(&acc[(mi * 8 + nb * 2 + 1) * 4], am[mi], bm[nb][1], bm[nb][3]);
                }
        }
        if (++j == 2) {   // key chunk complete
            j = 0;
#pragma unroll
            for (int mi = 0; mi < 2; mi++)
#pragma unroll
                for (int rh = 0; rh < 2; rh++) {
                    float pp = 0.f;
#pragma unroll
                    for (int nb = 0; nb < 4; nb++)
#pragma unroll
                        for (int jj = 0; jj < 2; jj++)
                            pp += exp2pair(acc[(mi * 8 + nb * 2 + jj) * 4 + rh * 2 + 0],
                                           acc[(mi * 8 + nb * 2 + jj) * 4 + rh * 2 + 1]);
                    rsacc[mi * 2 + rh] += pp;
                }
            if (cnum == (int)blockIdx.x) {   // diagonal chunk
#pragma unroll
                for (int mi = 0; mi < 2; mi++)
#pragma unroll
                    for (int nb = 0; nb < 4; nb++)
#pragma unroll
                        for (int jj = 0; jj < 2; jj++)
#pragma unroll
                            for (int rh = 0; rh < 2; rh++) {
                                int row = wm * 32 + mi * 16 + l4 + rh * 8;
                                int col = wn * 64 + nb * 16 + jj * 8 + lm * 2;
                                if (row == col)
                                    diag[row] = acc[(mi * 8 + nb * 2 + jj) * 4 + rh * 2 + 0];
                                if (row == col + 1)
                                    diag[row] = acc[(mi * 8 + nb * 2 + jj) * 4 + rh * 2 + 1];
                            }
            }
            cnum++;
#pragma unroll
            for (int i = 0; i < 64; i++) acc[i] = 0.f;
        }
    }

    // rowsum reduce -> w in smem (diag path stays full-precision fp32)
#pragma unroll
    for (int i = 0; i < 4; i++) {
        rsacc[i] += __shfl_xor_sync(0xffffffffu, rsacc[i], 1);
        rsacc[i] += __shfl_xor_sync(0xffffffffu, rsacc[i], 2);
    }
    if (lm == 0) {
#pragma unroll
        for (int mi = 0; mi < 2; mi++)
#pragma unroll
            for (int rh = 0; rh < 2; rh++)
                tmp[wn * 128 + wm * 32 + mi * 16 + rh * 8 + l4] = rsacc[mi * 2 + rh];
    }
    __syncthreads();
    if (tid < 128) {
        float sum = tmp[tid] + tmp[128 + tid];
        wrow[tid] = __expf(diag[tid] * scale - logf(sum)) * ASCALE;
    }
    __syncthreads();

    // fused scaled wV
#pragma unroll
    for (int i = 0; i < 8; i++) {
        int u = tid + i * 256;
        int r = u >> 4, ch = u & 15;
        size_t idx = (((size_t)(b * Ssz + q0 + r)) << 11) + h * DHsz + ch * 8;
        float wv = wrow[r];
        __half2 vin[4];
        *(uint4*)vin = *(const uint4*)(g_Vh + idx);
        __half2 vout[4];
#pragma unroll
        for (int q = 0; q < 4; q++) {
            float2 f = __half22float2(vin[q]);
            vout[q] = __floats2half2_rn(f.x * wv, f.y * wv);
        }
        *(uint4*)(g_Ah + idx) = *(uint4*)vout;
    }
}

// ---------------- launch ----------------
extern "C" void kernel_launch(void* const* d_in, const int* in_sizes, int n_in,
                              void* d_out, int out_size) {
    const float* x  = (const float*)d_in[0];
    const float* rc = (const float*)d_in[1];
    const float* rs = (const float*)d_in[2];
    const float* Wq = (const float*)d_in[3];
    const float* Wk = (const float*)d_in[4];
    const float* Wv = (const float*)d_in[5];
    const float* Wo = (const float*)d_in[6];
    float* out = (float*)d_out;

    cudaFuncSetAttribute(gemm_mma, cudaFuncAttributeMaxDynamicSharedMemorySize, G_SMEM);
    cudaFuncSetAttribute(lse_mma, cudaFuncAttributeMaxDynamicSharedMemorySize, L_SMEM);

    conv_all<<<(XCHUNKS + 4 * WCHUNKS) / 256, 256>>>(x, Wq, Wk, Wv, Wo);      // 1
    gemm_mma<<<dim3(Msz / 128, 48), 256, G_SMEM>>>(rc, rs, nullptr, 0);       // 2: QKV merged
    lse_mma<<<dim3(Ssz / 128, Hn, Bsz), 256, L_SMEM>>>();                     // 3: lse+w+A
    gemm_mma<<<dim3(Msz / 128, Dsz / 128), 256, G_SMEM>>>(rc, rs, out, 3);    // 4: A@Wo^T
}